// round 2
// baseline (speedup 1.0000x reference)
#include <cuda_runtime.h>

#define B 16
#define CIN 16
#define DD 16
#define HH 128
#define WW 128
#define COUT 64
#define HW (HH*WW)

// ---- device scratch (no allocs allowed) ----
__device__ float g_s[B*CIN*HW];        // depth-summed x: [b][c][h][w]  (16.8 MB)
__device__ float g_w[48*9*COUT];       // transposed weights [ci48][k9][co64], sign folded

// ---- f32x2 helpers (Blackwell packed fp32 pipe: 2x FFMA throughput) ----
__device__ __forceinline__ unsigned long long pk2(float lo, float hi) {
    unsigned long long r;
    asm("mov.b64 %0, {%1, %2};" : "=l"(r) : "f"(lo), "f"(hi));
    return r;
}
__device__ __forceinline__ void fma2(unsigned long long& d, unsigned long long a, unsigned long long b) {
    asm("fma.rn.f32x2 %0, %1, %2, %0;" : "+l"(d) : "l"(a), "l"(b));
}
__device__ __forceinline__ void unp2(unsigned long long v, float& a, float& b) {
    asm("mov.b64 {%0, %1}, %2;" : "=f"(a), "=f"(b) : "l"(v));
}

// ============================================================
// Kernel 0: transpose weights to [ci48][kh][kw][co64], fold signs
// ============================================================
__global__ void prep_w(const float* __restrict__ wsum,
                       const float* __restrict__ wfront,
                       const float* __restrict__ wback) {
    int idx = blockIdx.x * blockDim.x + threadIdx.x;
    if (idx >= 48*9*COUT) return;
    int co = idx & 63;
    int k  = (idx >> 6) % 9;
    int ci = idx / (9*64);
    int grp = ci >> 4;
    int c   = ci & 15;
    const float* src = (grp == 0) ? wsum : (grp == 1 ? wfront : wback);
    float v = src[(co*CIN + c)*9 + k];
    if (grp) v = -v;
    g_w[(ci*9 + k)*COUT + co] = v;
}

// ============================================================
// Kernel 1: depth sum (DRAM-bound, float4)
// ============================================================
__global__ void depth_sum(const float* __restrict__ x) {
    int i = blockIdx.x * blockDim.x + threadIdx.x;
    if (i >= B*CIN*(HW/4)) return;
    int bc = i / (HW/4);
    int r  = i - bc*(HW/4);
    const float4* p = reinterpret_cast<const float4*>(x) + (size_t)bc*DD*(HW/4) + r;
    float4 acc = p[0];
    #pragma unroll
    for (int z = 1; z < DD; z++) {
        float4 v = p[(size_t)z*(HW/4)];
        acc.x += v.x; acc.y += v.y; acc.z += v.z; acc.w += v.w;
    }
    reinterpret_cast<float4*>(g_s)[(size_t)bc*(HW/4) + r] = acc;
}

// ============================================================
// Kernel 2: fused 3x3 conv (48->64) + bias + channel softmax + tanh
//
// Block = 8x32 pixel tile, 512 threads (4 warps/SMSP for latency hiding).
// Warp w: cog = w>>1 (8 couts = 4 f32x2 cout-pairs), pxh = w&1.
// Lane pg: pixel group g = pxh*32+pg -> prow = g>>3, pcol = (g&7)*4. 4 pixels.
// Thread = 4 cout-pairs x 4 pixels = 16 u64 accumulators.
// Weight pair loads = aligned LDS broadcasts (no packing movs).
// Patch pitch 35: lane addr (3*prow + 4*pcl) mod 32 distinct -> conflict-free.
// ============================================================
#define T_H 8
#define T_W 32
#define P_ROWS 10
#define P_PITCH 35
#define P_CI_STRIDE (P_ROWS*P_PITCH)          // 350
#define SMEM_W_FLOATS (48*9*64)               // 27648
#define UNION_OFF (SMEM_W_FLOATS + 64)
#define UNION_FLOATS (48*P_CI_STRIDE)         // 16800 (> 256*65 = 16640)
#define SMEM_FLOATS (UNION_OFF + UNION_FLOATS)
#define SMEM_BYTES (SMEM_FLOATS*4)            // 178048 B

__global__ void __launch_bounds__(512, 1)
conv_softmax(const float* __restrict__ x,
             const float* __restrict__ bias,
             float* __restrict__ out) {
    extern __shared__ float sm[];
    float* sw    = sm;
    float* sb    = sm + SMEM_W_FLOATS;
    float* patch = sm + UNION_OFF;

    const int tid  = threadIdx.x;
    const int b    = blockIdx.y;
    const int tile = blockIdx.x;              // 0..63
    const int th0  = (tile >> 2) * T_H;
    const int tw0  = (tile & 3) * T_W;

    // load weights (float4) + bias into smem
    {
        const float4* wg = reinterpret_cast<const float4*>(g_w);
        float4* wsm = reinterpret_cast<float4*>(sw);
        for (int i = tid; i < SMEM_W_FLOATS/4; i += 512) wsm[i] = wg[i];
        if (tid < 64) sb[tid] = bias[tid];
    }

    // load input patch [48][10][35], zero-padded at image borders
    for (int i = tid; i < 48*P_ROWS*34; i += 512) {
        int ci  = i / (P_ROWS*34);
        int rem = i - ci*(P_ROWS*34);
        int r = rem / 34, c = rem - (rem/34)*34;
        int gh = th0 + r - 1, gw = tw0 + c - 1;
        float v = 0.0f;
        if ((unsigned)gh < HH && (unsigned)gw < WW) {
            int grp = ci >> 4, ch = ci & 15;
            const float* src;
            if (grp == 0) src = g_s + (size_t)(b*CIN + ch)*HW;
            else          src = x + ((size_t)(b*CIN + ch)*DD + (grp == 1 ? 0 : DD-1))*HW;
            v = src[gh*WW + gw];
        }
        patch[ci*P_CI_STRIDE + r*P_PITCH + c] = v;
    }
    __syncthreads();

    const int w    = tid >> 5;
    const int pg   = tid & 31;
    const int cog  = w >> 1;                  // 0..7 : couts cog*8..+8
    const int grpx = ((w & 1) << 5) + pg;     // pixel group 0..63
    const int prow = grpx >> 3;               // 0..7
    const int pcol = (grpx & 7) << 2;         // 0,4,..,28

    unsigned long long acc[4][4];             // [cout-pair][pixel]
    #pragma unroll
    for (int cp = 0; cp < 4; cp++)
        #pragma unroll
        for (int p = 0; p < 4; p++) acc[cp][p] = 0ULL;

    const float* wbase = sw + (cog << 3);

    for (int ci = 0; ci < 48; ci++) {
        const float* pb = patch + ci*P_CI_STRIDE + prow*P_PITCH + pcol;
        const float* wci = wbase + ci*9*64;
        #pragma unroll
        for (int kh = 0; kh < 3; kh++) {
            const float* ib = pb + kh*P_PITCH;
            unsigned long long d2[6];
            #pragma unroll
            for (int t = 0; t < 6; t++) {
                float v = ib[t];
                d2[t] = pk2(v, v);
            }
            const float* wr = wci + kh*3*64;
            #pragma unroll
            for (int kw = 0; kw < 3; kw++) {
                ulonglong2 wa = *reinterpret_cast<const ulonglong2*>(wr + kw*64);
                ulonglong2 wc = *reinterpret_cast<const ulonglong2*>(wr + kw*64 + 4);
                unsigned long long wp[4] = {wa.x, wa.y, wc.x, wc.y};
                #pragma unroll
                for (int p = 0; p < 4; p++)
                    #pragma unroll
                    for (int cp = 0; cp < 4; cp++)
                        fma2(acc[cp][p], wp[cp], d2[p + kw]);
            }
        }
    }
    __syncthreads();   // patch done; reuse as logits [pixel][co] pitch 65

    float* lg = patch;
    #pragma unroll
    for (int cp = 0; cp < 4; cp++) {
        int co = (cog << 3) + (cp << 1);
        #pragma unroll
        for (int p = 0; p < 4; p++) {
            float lo, hi;
            unp2(acc[cp][p], lo, hi);
            int px = (prow << 5) + pcol + p;
            lg[px*65 + co]     = lo;
            lg[px*65 + co + 1] = hi;
        }
    }
    __syncthreads();

    // epilogue: 2 threads per pixel, 32 channels each, shfl-combine
    const int px   = tid >> 1;
    const int half = tid & 1;
    const float* myl = lg + px*65 + (half << 5);
    const float* myb = sb + (half << 5);

    float ev[32];
    float mx = -3.4e38f;
    #pragma unroll
    for (int i = 0; i < 32; i++) {
        float v = myl[i] + myb[i];
        ev[i] = v;
        mx = fmaxf(mx, v);
    }
    mx = fmaxf(mx, __shfl_xor_sync(0xFFFFFFFFu, mx, 1));
    float s = 0.0f;
    #pragma unroll
    for (int i = 0; i < 32; i++) {
        float e = __expf(ev[i] - mx);
        ev[i] = e;
        s += e;
    }
    s += __shfl_xor_sync(0xFFFFFFFFu, s, 1);
    float inv = __fdividef(1.0f, s);

    int gh = th0 + (px >> 5);
    int gw = tw0 + (px & 31);
    float* ob = out + (size_t)b*COUT*HW + gh*WW + gw + (size_t)(half << 5)*HW;
    #pragma unroll
    for (int i = 0; i < 32; i++) {
        float p = ev[i] * inv;                 // in [0,1]
        float t = __expf(-2.0f * p);
        ob[(size_t)i*HW] = __fdividef(1.0f - t, 1.0f + t);
    }
}

// ============================================================
extern "C" void kernel_launch(void* const* d_in, const int* in_sizes, int n_in,
                              void* d_out, int out_size) {
    const float* x      = (const float*)d_in[0];
    const float* wsum   = (const float*)d_in[1];
    const float* wfront = (const float*)d_in[2];
    const float* wback  = (const float*)d_in[3];
    const float* bias   = (const float*)d_in[4];
    float* out = (float*)d_out;

    cudaFuncSetAttribute(conv_softmax, cudaFuncAttributeMaxDynamicSharedMemorySize, SMEM_BYTES);

    prep_w<<<(48*9*COUT + 255)/256, 256>>>(wsum, wfront, wback);
    depth_sum<<<(B*CIN*(HW/4) + 255)/256, 256>>>(x);
    dim3 grid(64, B);
    conv_softmax<<<grid, 512, SMEM_BYTES>>>(x, bias, out);
}